// round 2
// baseline (speedup 1.0000x reference)
#include <cuda_runtime.h>
#include <cuda_bf16.h>

// ---------------- problem constants ----------------
#define N_NODES 100000
#define N_EDGES 3200000
#define IN_F    500
#define HID     64
#define OUT_F   64
#define ALPHA   0.1f
#define K_ITERS 10

#define NSCAN_BLOCKS ((N_NODES + 1023) / 1024)   // 98

typedef unsigned long long u64;

// ---------------- static device scratch ----------------
__device__ float g_h1[N_NODES * HID];         // relu(x@W1+b1)
__device__ float g_h [N_NODES * OUT_F];       // MLP output
__device__ float g_z0[N_NODES * OUT_F];       // ping
__device__ float g_z1[N_NODES * OUT_F];       // pong
__device__ int   g_deg[N_NODES];
__device__ int   g_off[N_NODES + 1];
__device__ int   g_pos[N_NODES];
__device__ int2  g_edge[N_EDGES];             // (src, w bits) sorted by dst
__device__ int   g_bsum[NSCAN_BLOCKS];

// ---------------- f32x2 helpers ----------------
__device__ __forceinline__ u64 pack2(float x, float y) {
    u64 r; asm("mov.b64 %0, {%1, %2};" : "=l"(r) : "f"(x), "f"(y)); return r;
}
__device__ __forceinline__ void unpack2(float& x, float& y, u64 v) {
    asm("mov.b64 {%0, %1}, %2;" : "=f"(x), "=f"(y) : "l"(v));
}
#define FMA2(acc, a, b) asm("fma.rn.f32x2 %0, %1, %2, %0;" : "+l"(acc) : "l"(a), "l"(b))

// ---------------- CSR construction ----------------
__global__ void zero_deg_kernel() {
    int i = blockIdx.x * blockDim.x + threadIdx.x;
    if (i < N_NODES) g_deg[i] = 0;
}

__global__ void hist_kernel(const int* __restrict__ dst) {
    int i = blockIdx.x * blockDim.x + threadIdx.x;
    if (i * 4 + 3 < N_EDGES) {
        int4 d = ((const int4*)dst)[i];
        atomicAdd(&g_deg[d.x], 1);
        atomicAdd(&g_deg[d.y], 1);
        atomicAdd(&g_deg[d.z], 1);
        atomicAdd(&g_deg[d.w], 1);
    } else {
        for (int e = i * 4; e < N_EDGES; e++) atomicAdd(&g_deg[dst[e]], 1);
    }
}

__global__ void scan_local_kernel() {
    __shared__ int s[1024];
    int tid = threadIdx.x;
    int i = blockIdx.x * 1024 + tid;
    int v = (i < N_NODES) ? g_deg[i] : 0;
    s[tid] = v;
    __syncthreads();
    #pragma unroll
    for (int d = 1; d < 1024; d <<= 1) {
        int t = (tid >= d) ? s[tid - d] : 0;
        __syncthreads();
        s[tid] += t;
        __syncthreads();
    }
    if (i < N_NODES) g_off[i] = s[tid] - v;       // exclusive
    if (tid == 1023) g_bsum[blockIdx.x] = s[1023];
}

__global__ void scan_top_kernel() {
    if (threadIdx.x == 0 && blockIdx.x == 0) {
        int run = 0;
        for (int b = 0; b < NSCAN_BLOCKS; b++) {
            int t = g_bsum[b];
            g_bsum[b] = run;
            run += t;
        }
    }
}

__global__ void scan_add_kernel() {
    int i = blockIdx.x * 1024 + threadIdx.x;
    if (i < N_NODES) {
        int o = g_off[i] + g_bsum[blockIdx.x];
        g_off[i] = o;
        g_pos[i] = o;
    }
    if (blockIdx.x == 0 && threadIdx.x == 0) g_off[N_NODES] = N_EDGES;
}

__global__ void scatter_kernel(const int* __restrict__ src,
                               const int* __restrict__ dst,
                               const float* __restrict__ w) {
    int e = blockIdx.x * blockDim.x + threadIdx.x;
    if (e < N_EDGES) {
        int d = dst[e];
        int p = atomicAdd(&g_pos[d], 1);
        g_edge[p] = make_int2(src[e], __float_as_int(w[e]));
    }
}

// ---------------- GEMM: C[n,64] = act(A[n,K] @ W[K,64] + b) ----------------
// 256 threads = 8 warps; block computes 128 rows.
// Warp w: rows w*16 .. w*16+15. Lane: rh = lane>>4 (row half +0/+8),
// cg = lane&15 -> columns 4*cg .. 4*cg+3. Accumulators are f32x2 pairs.
template <bool RELU>
__global__ __launch_bounds__(256)
void gemm128_kernel(const float* __restrict__ A, const float* __restrict__ W,
                    const float* __restrict__ bias, float* __restrict__ C,
                    int nrows, int K) {
    __shared__ u64 xs[128 * 32];   // x duplicated (v,v) per element
    __shared__ u64 ws[32 * 32];    // [kk][p] = (W[kk][2p], W[kk][2p+1])

    const int tid  = threadIdx.x;
    const int w    = tid >> 5;
    const int lane = tid & 31;
    const int rh   = lane >> 4;
    const int cg   = lane & 15;
    const int rbase = w * 16 + rh * 8;      // local row base for this lane
    const int row0  = blockIdx.x * 128;

    u64 acc[8][2];
    #pragma unroll
    for (int r = 0; r < 8; r++) { acc[r][0] = 0ull; acc[r][1] = 0ull; }

    for (int ko = 0; ko < K; ko += 32) {
        // stage x tile (coalesced: warp reads one row's 32 k values)
        #pragma unroll
        for (int i = tid; i < 128 * 32; i += 256) {
            int r  = i >> 5;
            int kk = i & 31;
            int gr = row0 + r;
            int gk = ko + kk;
            float v = (gr < nrows && gk < K) ? A[(long)gr * K + gk] : 0.f;
            xs[r * 32 + kk] = pack2(v, v);
        }
        // stage W tile as column pairs
        #pragma unroll
        for (int i = tid; i < 32 * 32; i += 256) {
            int kk = i >> 5;
            int p  = i & 31;
            int gk = ko + kk;
            float w0 = 0.f, w1 = 0.f;
            if (gk < K) { w0 = W[gk * 64 + 2 * p]; w1 = W[gk * 64 + 2 * p + 1]; }
            ws[kk * 32 + p] = pack2(w0, w1);
        }
        __syncthreads();

        #pragma unroll
        for (int kk = 0; kk < 32; kk++) {
            ulonglong2 wv = *(const ulonglong2*)&ws[kk * 32 + 2 * cg];
            #pragma unroll
            for (int r = 0; r < 8; r++) {
                u64 xd = xs[(rbase + r) * 32 + kk];
                FMA2(acc[r][0], xd, wv.x);
                FMA2(acc[r][1], xd, wv.y);
            }
        }
        __syncthreads();
    }

    float4 b4 = *(const float4*)&bias[4 * cg];
    #pragma unroll
    for (int r = 0; r < 8; r++) {
        int row = row0 + rbase + r;
        if (row < nrows) {
            float c0, c1, c2, c3;
            unpack2(c0, c1, acc[r][0]);
            unpack2(c2, c3, acc[r][1]);
            c0 += b4.x; c1 += b4.y; c2 += b4.z; c3 += b4.w;
            if (RELU) {
                c0 = fmaxf(c0, 0.f); c1 = fmaxf(c1, 0.f);
                c2 = fmaxf(c2, 0.f); c3 = fmaxf(c3, 0.f);
            }
            *(float4*)&C[(long)row * 64 + 4 * cg] = make_float4(c0, c1, c2, c3);
        }
    }
}

// ---------------- APPNP propagation (pull, warp per node) ----------------
// lane owns columns (2*lane, 2*lane+1); one LDG.64 per edge per lane.
__global__ __launch_bounds__(256)
void prop_kernel(const float2* __restrict__ zin, const float2* __restrict__ h,
                 float2* __restrict__ zout) {
    int gtid = blockIdx.x * blockDim.x + threadIdx.x;
    int node = gtid >> 5;
    int lane = threadIdx.x & 31;
    if (node >= N_NODES) return;

    int beg = g_off[node];
    int end = g_off[node + 1];

    float a0 = 0.f, a1 = 0.f;
    for (int e = beg; e < end; e += 32) {
        int idx = e + lane;
        int2 sw = (idx < end) ? g_edge[idx] : make_int2(0, 0);
        int rem = end - e;
        int cnt = rem < 32 ? rem : 32;
        #pragma unroll 4
        for (int j = 0; j < cnt; j++) {
            int   sj = __shfl_sync(0xffffffffu, sw.x, j);
            float wj = __int_as_float(__shfl_sync(0xffffffffu, sw.y, j));
            float2 v = __ldg(&zin[(long)sj * 32 + lane]);
            a0 = fmaf(wj, v.x, a0);
            a1 = fmaf(wj, v.y, a1);
        }
    }
    long o = (long)node * 32 + lane;
    float2 hv = h[o];
    zout[o] = make_float2(fmaf(1.0f - ALPHA, a0, ALPHA * hv.x),
                          fmaf(1.0f - ALPHA, a1, ALPHA * hv.y));
}

// ---------------- launch ----------------
extern "C" void kernel_launch(void* const* d_in, const int* in_sizes, int n_in,
                              void* d_out, int out_size) {
    const float* x    = (const float*)d_in[0];
    const int*   esrc = (const int*)d_in[1];
    const int*   edst = (const int*)d_in[2];
    const float* ew   = (const float*)d_in[3];
    const float* W1   = (const float*)d_in[4];
    const float* b1   = (const float*)d_in[5];
    const float* W2   = (const float*)d_in[6];
    const float* b2   = (const float*)d_in[7];
    float* out = (float*)d_out;

    // side stream + fork/join events, created once (first call is the
    // non-captured correctness run; identical work is launched every call)
    static cudaStream_t s_side = nullptr;
    static cudaEvent_t  s_evFork = nullptr, s_evJoin = nullptr;
    if (!s_side) {
        cudaStreamCreateWithFlags(&s_side, cudaStreamNonBlocking);
        cudaEventCreateWithFlags(&s_evFork, cudaEventDisableTiming);
        cudaEventCreateWithFlags(&s_evJoin, cudaEventDisableTiming);
    }

    float *h1_p, *h_p, *z0_p, *z1_p;
    cudaGetSymbolAddress((void**)&h1_p, g_h1);
    cudaGetSymbolAddress((void**)&h_p,  g_h);
    cudaGetSymbolAddress((void**)&z0_p, g_z0);
    cudaGetSymbolAddress((void**)&z1_p, g_z1);

    // --- fork: CSR build on side stream, concurrent with MLP GEMMs ---
    cudaEventRecord(s_evFork, 0);
    cudaStreamWaitEvent(s_side, s_evFork, 0);

    zero_deg_kernel<<<NSCAN_BLOCKS, 1024, 0, s_side>>>();
    hist_kernel<<<(N_EDGES / 4 + 255) / 256, 256, 0, s_side>>>(edst);
    scan_local_kernel<<<NSCAN_BLOCKS, 1024, 0, s_side>>>();
    scan_top_kernel<<<1, 32, 0, s_side>>>();
    scan_add_kernel<<<NSCAN_BLOCKS, 1024, 0, s_side>>>();
    scatter_kernel<<<(N_EDGES + 255) / 256, 256, 0, s_side>>>(esrc, edst, ew);
    cudaEventRecord(s_evJoin, s_side);

    // --- MLP encoder on main stream ---
    int gblocks = (N_NODES + 127) / 128;
    gemm128_kernel<true ><<<gblocks, 256>>>(x,    W1, b1, h1_p, N_NODES, IN_F);
    gemm128_kernel<false><<<gblocks, 256>>>(h1_p, W2, b2, h_p,  N_NODES, HID);

    // --- join, then K propagation steps, last writes d_out ---
    cudaStreamWaitEvent(0, s_evJoin, 0);

    int pblocks = (N_NODES * 32 + 255) / 256;
    const float* zin = h_p;
    for (int k = 0; k < K_ITERS; k++) {
        float* zout = (k == K_ITERS - 1) ? out : ((k & 1) ? z1_p : z0_p);
        prop_kernel<<<pblocks, 256>>>((const float2*)zin, (const float2*)h_p,
                                      (float2*)zout);
        zin = zout;
    }
}

// round 3
// speedup vs baseline: 1.0663x; 1.0663x over previous
#include <cuda_runtime.h>
#include <cuda_bf16.h>

// ---------------- problem constants ----------------
#define N_NODES 100000
#define N_EDGES 3200000
#define IN_F    500
#define HID     64
#define OUT_F   64
#define ALPHA   0.1f
#define K_ITERS 10

#define NSCAN_BLOCKS ((N_NODES + 1023) / 1024)   // 98
#define KK 8                                      // gemm k-tile

typedef unsigned long long u64;

// ---------------- static device scratch ----------------
__device__ float g_h1[N_NODES * HID];
__device__ float g_h [N_NODES * OUT_F];
__device__ float g_z0[N_NODES * OUT_F];
__device__ float g_z1[N_NODES * OUT_F];
__device__ int   g_deg[N_NODES];
__device__ int   g_off[N_NODES + 1];
__device__ int   g_pos[N_NODES];
__device__ int2  g_edge[N_EDGES];
__device__ int   g_bsum[NSCAN_BLOCKS];

// ---------------- f32x2 helpers ----------------
__device__ __forceinline__ u64 pack2(float x, float y) {
    u64 r; asm("mov.b64 %0, {%1, %2};" : "=l"(r) : "f"(x), "f"(y)); return r;
}
__device__ __forceinline__ void unpack2(float& x, float& y, u64 v) {
    asm("mov.b64 {%0, %1}, %2;" : "=f"(x), "=f"(y) : "l"(v));
}
#define FMA2(acc, a, b) asm("fma.rn.f32x2 %0, %1, %2, %0;" : "+l"(acc) : "l"(a), "l"(b))

// ---------------- CSR construction ----------------
__global__ void zero_deg_kernel() {
    int i = blockIdx.x * blockDim.x + threadIdx.x;
    if (i < N_NODES) g_deg[i] = 0;
}

__global__ void hist_kernel(const int* __restrict__ dst) {
    int i = blockIdx.x * blockDim.x + threadIdx.x;
    if (i * 4 + 3 < N_EDGES) {
        int4 d = ((const int4*)dst)[i];
        atomicAdd(&g_deg[d.x], 1);
        atomicAdd(&g_deg[d.y], 1);
        atomicAdd(&g_deg[d.z], 1);
        atomicAdd(&g_deg[d.w], 1);
    } else {
        for (int e = i * 4; e < N_EDGES; e++) atomicAdd(&g_deg[dst[e]], 1);
    }
}

__global__ void scan_local_kernel() {
    __shared__ int s[1024];
    int tid = threadIdx.x;
    int i = blockIdx.x * 1024 + tid;
    int v = (i < N_NODES) ? g_deg[i] : 0;
    s[tid] = v;
    __syncthreads();
    #pragma unroll
    for (int d = 1; d < 1024; d <<= 1) {
        int t = (tid >= d) ? s[tid - d] : 0;
        __syncthreads();
        s[tid] += t;
        __syncthreads();
    }
    if (i < N_NODES) g_off[i] = s[tid] - v;
    if (tid == 1023) g_bsum[blockIdx.x] = s[1023];
}

__global__ void scan_top_kernel() {
    if (threadIdx.x == 0 && blockIdx.x == 0) {
        int run = 0;
        for (int b = 0; b < NSCAN_BLOCKS; b++) {
            int t = g_bsum[b];
            g_bsum[b] = run;
            run += t;
        }
    }
}

__global__ void scan_add_kernel() {
    int i = blockIdx.x * 1024 + threadIdx.x;
    if (i < N_NODES) {
        int o = g_off[i] + g_bsum[blockIdx.x];
        g_off[i] = o;
        g_pos[i] = o;
    }
    if (blockIdx.x == 0 && threadIdx.x == 0) g_off[N_NODES] = N_EDGES;
}

__global__ void scatter_kernel(const int* __restrict__ src,
                               const int* __restrict__ dst,
                               const float* __restrict__ w) {
    int e = blockIdx.x * blockDim.x + threadIdx.x;
    if (e < N_EDGES) {
        int d = dst[e];
        int p = atomicAdd(&g_pos[d], 1);
        g_edge[p] = make_int2(src[e], __float_as_int(w[e]));
    }
}

// ---------------- GEMM: C[n,64] = act(A[n,K] @ W[K,64] + b) ----------------
// 256 threads / 8 warps; block = 128 rows x 64 cols.
// Warp w: rows w*16..w*16+15; lane: rh=lane>>4 (8-row half), cg=lane&15 ->
// cols 4cg..4cg+3. W tile lives in registers; x read via LDS.128 (2 k per
// load, 16-lane broadcast -> 1 wavefront). FMA2 (f32x2) is the hot op.
template <bool RELU>
__global__ __launch_bounds__(256)
void gemm128_kernel(const float* __restrict__ A, const float* __restrict__ W,
                    const float* __restrict__ bias, float* __restrict__ C,
                    int nrows, int K) {
    __shared__ __align__(16) u64 xs[128 * KK];   // (v,v) duplicated, 8 KB
    __shared__ __align__(16) u64 ws[KK * 32];    // (W[k][2p],W[k][2p+1]), 2 KB

    const int tid  = threadIdx.x;
    const int w    = tid >> 5;
    const int lane = tid & 31;
    const int rh   = lane >> 4;
    const int cg   = lane & 15;
    const int rbase = w * 16 + rh * 8;
    const int row0  = blockIdx.x * 128;

    u64 acc[8][2];
    #pragma unroll
    for (int r = 0; r < 8; r++) { acc[r][0] = 0ull; acc[r][1] = 0ull; }

    const int ktiles = (K + KK - 1) / KK;
    for (int t = 0; t < ktiles; t++) {
        const int ko = t * KK;
        // stage x tile (bounds-padded with 0)
        #pragma unroll
        for (int i = tid; i < 128 * KK; i += 256) {
            int r  = i >> 3;
            int kk = i & 7;
            int gr = row0 + r;
            int gk = ko + kk;
            float v = (gr < nrows && gk < K) ? __ldg(&A[(long)gr * K + gk]) : 0.f;
            xs[r * KK + kk] = pack2(v, v);
        }
        // stage W tile
        if (tid < KK * 32) {
            int kk = tid >> 5;
            int p  = tid & 31;
            int gk = ko + kk;
            float w0 = 0.f, w1 = 0.f;
            if (gk < K) { w0 = W[gk * 64 + 2 * p]; w1 = W[gk * 64 + 2 * p + 1]; }
            ws[kk * 32 + p] = pack2(w0, w1);
        }
        __syncthreads();

        // W tile -> registers (one LDS.128 per kk)
        u64 wr[KK][2];
        #pragma unroll
        for (int kk = 0; kk < KK; kk++) {
            ulonglong2 wv = *(const ulonglong2*)&ws[kk * 32 + 2 * cg];
            wr[kk][0] = wv.x; wr[kk][1] = wv.y;
        }

        #pragma unroll
        for (int kk2 = 0; kk2 < KK / 2; kk2++) {
            #pragma unroll
            for (int r = 0; r < 8; r++) {
                ulonglong2 xq = *(const ulonglong2*)&xs[(rbase + r) * KK + 2 * kk2];
                FMA2(acc[r][0], xq.x, wr[2 * kk2][0]);
                FMA2(acc[r][1], xq.x, wr[2 * kk2][1]);
                FMA2(acc[r][0], xq.y, wr[2 * kk2 + 1][0]);
                FMA2(acc[r][1], xq.y, wr[2 * kk2 + 1][1]);
            }
        }
        __syncthreads();
    }

    float4 b4 = *(const float4*)&bias[4 * cg];
    #pragma unroll
    for (int r = 0; r < 8; r++) {
        int row = row0 + rbase + r;
        if (row < nrows) {
            float c0, c1, c2, c3;
            unpack2(c0, c1, acc[r][0]);
            unpack2(c2, c3, acc[r][1]);
            c0 += b4.x; c1 += b4.y; c2 += b4.z; c3 += b4.w;
            if (RELU) {
                c0 = fmaxf(c0, 0.f); c1 = fmaxf(c1, 0.f);
                c2 = fmaxf(c2, 0.f); c3 = fmaxf(c3, 0.f);
            }
            *(float4*)&C[(long)row * 64 + 4 * cg] = make_float4(c0, c1, c2, c3);
        }
    }
}

// ---------------- APPNP propagation (pull, warp per node) ----------------
__global__ __launch_bounds__(256)
void prop_kernel(const float2* __restrict__ zin, const float2* __restrict__ h,
                 float2* __restrict__ zout) {
    int gtid = blockIdx.x * blockDim.x + threadIdx.x;
    int node = gtid >> 5;
    int lane = threadIdx.x & 31;
    if (node >= N_NODES) return;

    int beg = g_off[node];
    int end = g_off[node + 1];

    float a0 = 0.f, a1 = 0.f;
    int e = beg;
    // full 32-edge batches: fully unrolled, no per-edge bounds check
    for (; e + 32 <= end; e += 32) {
        int2 sw = g_edge[e + lane];
        #pragma unroll
        for (int j = 0; j < 32; j++) {
            int   sj = __shfl_sync(0xffffffffu, sw.x, j);
            float wj = __int_as_float(__shfl_sync(0xffffffffu, sw.y, j));
            float2 v = __ldg(&zin[(long)sj * 32 + lane]);
            a0 = fmaf(wj, v.x, a0);
            a1 = fmaf(wj, v.y, a1);
        }
    }
    if (e < end) {
        int idx = e + lane;
        int2 sw = (idx < end) ? g_edge[idx] : make_int2(0, 0);
        int cnt = end - e;
        for (int j = 0; j < cnt; j++) {
            int   sj = __shfl_sync(0xffffffffu, sw.x, j);
            float wj = __int_as_float(__shfl_sync(0xffffffffu, sw.y, j));
            float2 v = __ldg(&zin[(long)sj * 32 + lane]);
            a0 = fmaf(wj, v.x, a0);
            a1 = fmaf(wj, v.y, a1);
        }
    }
    long o = (long)node * 32 + lane;
    float2 hv = h[o];
    zout[o] = make_float2(fmaf(1.0f - ALPHA, a0, ALPHA * hv.x),
                          fmaf(1.0f - ALPHA, a1, ALPHA * hv.y));
}

// ---------------- launch ----------------
extern "C" void kernel_launch(void* const* d_in, const int* in_sizes, int n_in,
                              void* d_out, int out_size) {
    const float* x    = (const float*)d_in[0];
    const int*   esrc = (const int*)d_in[1];
    const int*   edst = (const int*)d_in[2];
    const float* ew   = (const float*)d_in[3];
    const float* W1   = (const float*)d_in[4];
    const float* b1   = (const float*)d_in[5];
    const float* W2   = (const float*)d_in[6];
    const float* b2   = (const float*)d_in[7];
    float* out = (float*)d_out;

    static cudaStream_t s_side = nullptr;
    static cudaEvent_t  s_evFork = nullptr, s_evJoin = nullptr;
    if (!s_side) {
        cudaStreamCreateWithFlags(&s_side, cudaStreamNonBlocking);
        cudaEventCreateWithFlags(&s_evFork, cudaEventDisableTiming);
        cudaEventCreateWithFlags(&s_evJoin, cudaEventDisableTiming);
    }

    float *h1_p, *h_p, *z0_p, *z1_p;
    cudaGetSymbolAddress((void**)&h1_p, g_h1);
    cudaGetSymbolAddress((void**)&h_p,  g_h);
    cudaGetSymbolAddress((void**)&z0_p, g_z0);
    cudaGetSymbolAddress((void**)&z1_p, g_z1);

    // --- fork: CSR build on side stream, concurrent with MLP GEMMs ---
    cudaEventRecord(s_evFork, 0);
    cudaStreamWaitEvent(s_side, s_evFork, 0);

    zero_deg_kernel<<<NSCAN_BLOCKS, 1024, 0, s_side>>>();
    hist_kernel<<<(N_EDGES / 4 + 255) / 256, 256, 0, s_side>>>(edst);
    scan_local_kernel<<<NSCAN_BLOCKS, 1024, 0, s_side>>>();
    scan_top_kernel<<<1, 32, 0, s_side>>>();
    scan_add_kernel<<<NSCAN_BLOCKS, 1024, 0, s_side>>>();
    scatter_kernel<<<(N_EDGES + 255) / 256, 256, 0, s_side>>>(esrc, edst, ew);
    cudaEventRecord(s_evJoin, s_side);

    // --- MLP encoder on main stream ---
    int gblocks = (N_NODES + 127) / 128;
    gemm128_kernel<true ><<<gblocks, 256>>>(x,    W1, b1, h1_p, N_NODES, IN_F);
    gemm128_kernel<false><<<gblocks, 256>>>(h1_p, W2, b2, h_p,  N_NODES, HID);

    // --- join, then K propagation steps, last writes d_out ---
    cudaStreamWaitEvent(0, s_evJoin, 0);

    int pblocks = (N_NODES * 32 + 255) / 256;
    const float* zin = h_p;
    for (int k = 0; k < K_ITERS; k++) {
        float* zout = (k == K_ITERS - 1) ? out : ((k & 1) ? z1_p : z0_p);
        prop_kernel<<<pblocks, 256>>>((const float2*)zin, (const float2*)h_p,
                                      (float2*)zout);
        zin = zout;
    }
}

// round 4
// speedup vs baseline: 1.1399x; 1.0690x over previous
#include <cuda_runtime.h>
#include <cuda_bf16.h>
#include <cuda_fp16.h>
#include <math.h>

// ---------------- problem constants ----------------
#define N_NODES 100000
#define N_EDGES 3200000
#define IN_F    500
#define HID     64
#define OUT_F   64
#define ALPHA   0.1f
#define K_ITERS 10

#define NSCAN_BLOCKS ((N_NODES + 1023) / 1024)   // 98
#define KK 8                                      // gemm k-tile
#define SCALE_S 0.0625                            // 1/16 per-iteration z scaling

typedef unsigned long long u64;

// ---------------- static device scratch ----------------
__device__ float  g_h1[N_NODES * HID];
__device__ float  g_h [N_NODES * OUT_F];
__device__ __half g_ya[N_NODES * OUT_F];          // fp16 scaled iterate ping
__device__ __half g_yb[N_NODES * OUT_F];          // fp16 scaled iterate pong
__device__ int    g_deg[N_NODES];
__device__ int    g_off[N_NODES + 1];
__device__ int    g_pos[N_NODES];
__device__ int2   g_edge[N_EDGES];
__device__ int    g_bsum[NSCAN_BLOCKS];

// ---------------- f32x2 helpers ----------------
__device__ __forceinline__ u64 pack2(float x, float y) {
    u64 r; asm("mov.b64 %0, {%1, %2};" : "=l"(r) : "f"(x), "f"(y)); return r;
}
__device__ __forceinline__ void unpack2(float& x, float& y, u64 v) {
    asm("mov.b64 {%0, %1}, %2;" : "=f"(x), "=f"(y) : "l"(v));
}
#define FMA2(acc, a, b) asm("fma.rn.f32x2 %0, %1, %2, %0;" : "+l"(acc) : "l"(a), "l"(b))

// ---------------- CSR construction ----------------
__global__ void zero_deg_kernel() {
    int i = blockIdx.x * blockDim.x + threadIdx.x;
    if (i < N_NODES) g_deg[i] = 0;
}

__global__ void hist_kernel(const int* __restrict__ dst) {
    int i = blockIdx.x * blockDim.x + threadIdx.x;
    if (i * 4 + 3 < N_EDGES) {
        int4 d = ((const int4*)dst)[i];
        atomicAdd(&g_deg[d.x], 1);
        atomicAdd(&g_deg[d.y], 1);
        atomicAdd(&g_deg[d.z], 1);
        atomicAdd(&g_deg[d.w], 1);
    } else {
        for (int e = i * 4; e < N_EDGES; e++) atomicAdd(&g_deg[dst[e]], 1);
    }
}

__global__ void scan_local_kernel() {
    __shared__ int s[1024];
    int tid = threadIdx.x;
    int i = blockIdx.x * 1024 + tid;
    int v = (i < N_NODES) ? g_deg[i] : 0;
    s[tid] = v;
    __syncthreads();
    #pragma unroll
    for (int d = 1; d < 1024; d <<= 1) {
        int t = (tid >= d) ? s[tid - d] : 0;
        __syncthreads();
        s[tid] += t;
        __syncthreads();
    }
    if (i < N_NODES) g_off[i] = s[tid] - v;
    if (tid == 1023) g_bsum[blockIdx.x] = s[1023];
}

__global__ void scan_top_kernel() {
    if (threadIdx.x == 0 && blockIdx.x == 0) {
        int run = 0;
        for (int b = 0; b < NSCAN_BLOCKS; b++) {
            int t = g_bsum[b];
            g_bsum[b] = run;
            run += t;
        }
    }
}

__global__ void scan_add_kernel() {
    int i = blockIdx.x * 1024 + threadIdx.x;
    if (i < N_NODES) {
        int o = g_off[i] + g_bsum[blockIdx.x];
        g_off[i] = o;
        g_pos[i] = o;
    }
    if (blockIdx.x == 0 && threadIdx.x == 0) g_off[N_NODES] = N_EDGES;
}

__global__ void scatter_kernel(const int* __restrict__ src,
                               const int* __restrict__ dst,
                               const float* __restrict__ w) {
    int e = blockIdx.x * blockDim.x + threadIdx.x;
    if (e < N_EDGES) {
        int d = dst[e];
        int p = atomicAdd(&g_pos[d], 1);
        g_edge[p] = make_int2(src[e], __float_as_int(w[e]));
    }
}

// ---------------- GEMM: C[n,64] = act(A[n,K] @ W[K,64] + b) ----------------
// 256 threads / 8 warps; block = 128 rows x 64 cols. f32x2 FMA2 main loop.
// Optionally also emits an fp16 copy of the output (y_0 for propagation).
template <bool RELU, bool WRITE_HALF>
__global__ __launch_bounds__(256)
void gemm128_kernel(const float* __restrict__ A, const float* __restrict__ W,
                    const float* __restrict__ bias, float* __restrict__ C,
                    __half* __restrict__ Yh, int nrows, int K) {
    __shared__ __align__(16) u64 xs[128 * KK];
    __shared__ __align__(16) u64 ws[KK * 32];

    const int tid  = threadIdx.x;
    const int w    = tid >> 5;
    const int lane = tid & 31;
    const int rh   = lane >> 4;
    const int cg   = lane & 15;
    const int rbase = w * 16 + rh * 8;
    const int row0  = blockIdx.x * 128;

    u64 acc[8][2];
    #pragma unroll
    for (int r = 0; r < 8; r++) { acc[r][0] = 0ull; acc[r][1] = 0ull; }

    const int ktiles = (K + KK - 1) / KK;
    for (int t = 0; t < ktiles; t++) {
        const int ko = t * KK;
        #pragma unroll
        for (int i = tid; i < 128 * KK; i += 256) {
            int r  = i >> 3;
            int kk = i & 7;
            int gr = row0 + r;
            int gk = ko + kk;
            float v = (gr < nrows && gk < K) ? __ldg(&A[(long)gr * K + gk]) : 0.f;
            xs[r * KK + kk] = pack2(v, v);
        }
        if (tid < KK * 32) {
            int kk = tid >> 5;
            int p  = tid & 31;
            int gk = ko + kk;
            float w0 = 0.f, w1 = 0.f;
            if (gk < K) { w0 = W[gk * 64 + 2 * p]; w1 = W[gk * 64 + 2 * p + 1]; }
            ws[kk * 32 + p] = pack2(w0, w1);
        }
        __syncthreads();

        u64 wr[KK][2];
        #pragma unroll
        for (int kk = 0; kk < KK; kk++) {
            ulonglong2 wv = *(const ulonglong2*)&ws[kk * 32 + 2 * cg];
            wr[kk][0] = wv.x; wr[kk][1] = wv.y;
        }

        #pragma unroll
        for (int kk2 = 0; kk2 < KK / 2; kk2++) {
            #pragma unroll
            for (int r = 0; r < 8; r++) {
                ulonglong2 xq = *(const ulonglong2*)&xs[(rbase + r) * KK + 2 * kk2];
                FMA2(acc[r][0], xq.x, wr[2 * kk2][0]);
                FMA2(acc[r][1], xq.x, wr[2 * kk2][1]);
                FMA2(acc[r][0], xq.y, wr[2 * kk2 + 1][0]);
                FMA2(acc[r][1], xq.y, wr[2 * kk2 + 1][1]);
            }
        }
        __syncthreads();
    }

    float4 b4 = *(const float4*)&bias[4 * cg];
    #pragma unroll
    for (int r = 0; r < 8; r++) {
        int row = row0 + rbase + r;
        if (row < nrows) {
            float c0, c1, c2, c3;
            unpack2(c0, c1, acc[r][0]);
            unpack2(c2, c3, acc[r][1]);
            c0 += b4.x; c1 += b4.y; c2 += b4.z; c3 += b4.w;
            if (RELU) {
                c0 = fmaxf(c0, 0.f); c1 = fmaxf(c1, 0.f);
                c2 = fmaxf(c2, 0.f); c3 = fmaxf(c3, 0.f);
            }
            *(float4*)&C[(long)row * 64 + 4 * cg] = make_float4(c0, c1, c2, c3);
            if (WRITE_HALF) {
                long yi = (long)row * 64 + 4 * cg;
                *(__half2*)&Yh[yi]     = __floats2half2_rn(c0, c1);
                *(__half2*)&Yh[yi + 2] = __floats2half2_rn(c2, c3);
            }
        }
    }
}

// ---------------- APPNP propagation (fp16 scaled iterate) ----------------
// yout = c1 * (A yin) + c2 * h.  Non-final: store fp16; final: store fp32.
// lane owns columns (2l, 2l+1): one half2 (4B) per edge per lane -> 128B/row.
template <bool FINAL>
__global__ __launch_bounds__(256)
void prop_kernel(const __half2* __restrict__ yin, const float2* __restrict__ h,
                 __half2* __restrict__ yout, float2* __restrict__ fout,
                 float c1, float c2) {
    int gtid = blockIdx.x * blockDim.x + threadIdx.x;
    int node = gtid >> 5;
    int lane = threadIdx.x & 31;
    if (node >= N_NODES) return;

    int beg = g_off[node];
    int end = g_off[node + 1];

    float a0 = 0.f, a1 = 0.f;
    int e = beg;
    for (; e + 32 <= end; e += 32) {
        int2 sw = g_edge[e + lane];
        #pragma unroll
        for (int j = 0; j < 32; j++) {
            int   sj = __shfl_sync(0xffffffffu, sw.x, j);
            float wj = __int_as_float(__shfl_sync(0xffffffffu, sw.y, j));
            float2 v = __half22float2(__ldg(&yin[(long)sj * 32 + lane]));
            a0 = fmaf(wj, v.x, a0);
            a1 = fmaf(wj, v.y, a1);
        }
    }
    if (e < end) {
        int idx = e + lane;
        int2 sw = (idx < end) ? g_edge[idx] : make_int2(0, 0);
        int cnt = end - e;
        for (int j = 0; j < cnt; j++) {
            int   sj = __shfl_sync(0xffffffffu, sw.x, j);
            float wj = __int_as_float(__shfl_sync(0xffffffffu, sw.y, j));
            float2 v = __half22float2(__ldg(&yin[(long)sj * 32 + lane]));
            a0 = fmaf(wj, v.x, a0);
            a1 = fmaf(wj, v.y, a1);
        }
    }
    long o = (long)node * 32 + lane;
    float2 hv = h[o];
    float r0 = fmaf(c1, a0, c2 * hv.x);
    float r1 = fmaf(c1, a1, c2 * hv.y);
    if (FINAL) fout[o] = make_float2(r0, r1);
    else       yout[o] = __floats2half2_rn(r0, r1);
}

// ---------------- launch ----------------
extern "C" void kernel_launch(void* const* d_in, const int* in_sizes, int n_in,
                              void* d_out, int out_size) {
    const float* x    = (const float*)d_in[0];
    const int*   esrc = (const int*)d_in[1];
    const int*   edst = (const int*)d_in[2];
    const float* ew   = (const float*)d_in[3];
    const float* W1   = (const float*)d_in[4];
    const float* b1   = (const float*)d_in[5];
    const float* W2   = (const float*)d_in[6];
    const float* b2   = (const float*)d_in[7];
    float* out = (float*)d_out;

    static cudaStream_t s_side = nullptr;
    static cudaEvent_t  s_evFork = nullptr, s_evJoin = nullptr;
    if (!s_side) {
        cudaStreamCreateWithFlags(&s_side, cudaStreamNonBlocking);
        cudaEventCreateWithFlags(&s_evFork, cudaEventDisableTiming);
        cudaEventCreateWithFlags(&s_evJoin, cudaEventDisableTiming);
    }

    float *h1_p, *h_p;
    __half *ya_p, *yb_p;
    cudaGetSymbolAddress((void**)&h1_p, g_h1);
    cudaGetSymbolAddress((void**)&h_p,  g_h);
    cudaGetSymbolAddress((void**)&ya_p, g_ya);
    cudaGetSymbolAddress((void**)&yb_p, g_yb);

    // --- fork: CSR build on side stream, concurrent with MLP GEMMs ---
    cudaEventRecord(s_evFork, 0);
    cudaStreamWaitEvent(s_side, s_evFork, 0);

    zero_deg_kernel<<<NSCAN_BLOCKS, 1024, 0, s_side>>>();
    hist_kernel<<<(N_EDGES / 4 + 255) / 256, 256, 0, s_side>>>(edst);
    scan_local_kernel<<<NSCAN_BLOCKS, 1024, 0, s_side>>>();
    scan_top_kernel<<<1, 32, 0, s_side>>>();
    scan_add_kernel<<<NSCAN_BLOCKS, 1024, 0, s_side>>>();
    scatter_kernel<<<(N_EDGES + 255) / 256, 256, 0, s_side>>>(esrc, edst, ew);
    cudaEventRecord(s_evJoin, s_side);

    // --- MLP encoder on main stream (GEMM2 also emits y_0 = fp16(h)) ---
    int gblocks = (N_NODES + 127) / 128;
    gemm128_kernel<true,  false><<<gblocks, 256>>>(x,    W1, b1, h1_p, nullptr, N_NODES, IN_F);
    gemm128_kernel<false, true ><<<gblocks, 256>>>(h1_p, W2, b2, h_p,  ya_p,    N_NODES, HID);

    // --- join, then K propagation steps on scaled fp16 iterate ---
    cudaStreamWaitEvent(0, s_evJoin, 0);

    int pblocks = (N_NODES * 32 + 255) / 256;
    __half* yin  = ya_p;
    __half* yout = yb_p;
    for (int k = 0; k < K_ITERS; k++) {
        if (k < K_ITERS - 1) {
            // y_{k+1} = 0.9*S * (A y_k) + 0.1*S^{k+1} * h
            float c1 = (float)(0.9 * SCALE_S);
            float c2 = (float)(0.1 * pow(SCALE_S, (double)(k + 1)));
            prop_kernel<false><<<pblocks, 256>>>((const __half2*)yin,
                                                 (const float2*)h_p,
                                                 (__half2*)yout, nullptr, c1, c2);
            __half* t = yin; yin = yout; yout = t;
        } else {
            // z_K = 0.9 * S^{-(K-1)} * (A y_{K-1}) + 0.1 * h  (fp32 out)
            float c1 = (float)(0.9 * pow(1.0 / SCALE_S, (double)(K_ITERS - 1)));
            float c2 = 0.1f;
            prop_kernel<true><<<pblocks, 256>>>((const __half2*)yin,
                                                (const float2*)h_p,
                                                nullptr, (float2*)out, c1, c2);
        }
    }
}

// round 5
// speedup vs baseline: 1.2720x; 1.1159x over previous
#include <cuda_runtime.h>
#include <cuda_bf16.h>
#include <cuda_fp16.h>
#include <math.h>

// ---------------- problem constants ----------------
#define N_NODES 100000
#define N_EDGES 3200000
#define IN_F    500
#define HID     64
#define OUT_F   64
#define ALPHA   0.1f
#define K_ITERS 10

#define NSCAN_BLOCKS ((N_NODES + 1023) / 1024)   // 98
#define KK 8                                      // gemm k-tile
#define SCALE_S 0.0625                            // 1/16 per-iteration z scaling
#define WQ_SCALE 32767.0f
#define WQ_INV   (1.0f / 32767.0f)

typedef unsigned long long u64;

// ---------------- static device scratch ----------------
__device__ float    g_h1[N_NODES * HID];
__device__ float    g_h [N_NODES * OUT_F];
__device__ __half   g_ya[N_NODES * OUT_F];        // fp16 scaled iterate ping
__device__ __half   g_yb[N_NODES * OUT_F];        // fp16 scaled iterate pong
__device__ int      g_deg[N_NODES];
__device__ int      g_off[N_NODES + 1];
__device__ int      g_pos[N_NODES];
__device__ unsigned g_epk[N_EDGES];               // packed edge: w15 | src17
__device__ int      g_bsum[NSCAN_BLOCKS];

// ---------------- f32x2 helpers ----------------
__device__ __forceinline__ u64 pack2(float x, float y) {
    u64 r; asm("mov.b64 %0, {%1, %2};" : "=l"(r) : "f"(x), "f"(y)); return r;
}
__device__ __forceinline__ void unpack2(float& x, float& y, u64 v) {
    asm("mov.b64 {%0, %1}, %2;" : "=f"(x), "=f"(y) : "l"(v));
}
#define FMA2(acc, a, b) asm("fma.rn.f32x2 %0, %1, %2, %0;" : "+l"(acc) : "l"(a), "l"(b))

// ---------------- CSR construction ----------------
__global__ void zero_deg_kernel() {
    int i = blockIdx.x * blockDim.x + threadIdx.x;
    if (i < N_NODES) g_deg[i] = 0;
}

__global__ void hist_kernel(const int* __restrict__ dst) {
    int i = blockIdx.x * blockDim.x + threadIdx.x;
    if (i * 4 + 3 < N_EDGES) {
        int4 d = ((const int4*)dst)[i];
        atomicAdd(&g_deg[d.x], 1);
        atomicAdd(&g_deg[d.y], 1);
        atomicAdd(&g_deg[d.z], 1);
        atomicAdd(&g_deg[d.w], 1);
    } else {
        for (int e = i * 4; e < N_EDGES; e++) atomicAdd(&g_deg[dst[e]], 1);
    }
}

__global__ void scan_local_kernel() {
    __shared__ int s[1024];
    int tid = threadIdx.x;
    int i = blockIdx.x * 1024 + tid;
    int v = (i < N_NODES) ? g_deg[i] : 0;
    s[tid] = v;
    __syncthreads();
    #pragma unroll
    for (int d = 1; d < 1024; d <<= 1) {
        int t = (tid >= d) ? s[tid - d] : 0;
        __syncthreads();
        s[tid] += t;
        __syncthreads();
    }
    if (i < N_NODES) g_off[i] = s[tid] - v;
    if (tid == 1023) g_bsum[blockIdx.x] = s[1023];
}

__global__ void scan_top_kernel() {
    if (threadIdx.x == 0 && blockIdx.x == 0) {
        int run = 0;
        for (int b = 0; b < NSCAN_BLOCKS; b++) {
            int t = g_bsum[b];
            g_bsum[b] = run;
            run += t;
        }
    }
}

__global__ void scan_add_kernel() {
    int i = blockIdx.x * 1024 + threadIdx.x;
    if (i < N_NODES) {
        int o = g_off[i] + g_bsum[blockIdx.x];
        g_off[i] = o;
        g_pos[i] = o;
    }
    if (blockIdx.x == 0 && threadIdx.x == 0) g_off[N_NODES] = N_EDGES;
}

__global__ void scatter_kernel(const int* __restrict__ src,
                               const int* __restrict__ dst,
                               const float* __restrict__ w) {
    int e = blockIdx.x * blockDim.x + threadIdx.x;
    if (e < N_EDGES) {
        int d = dst[e];
        int p = atomicAdd(&g_pos[d], 1);
        unsigned q = (unsigned)__float2int_rn(w[e] * WQ_SCALE);
        g_epk[p] = (q << 17) | (unsigned)src[e];
    }
}

// ---------------- GEMM: C[n,64] = act(A[n,K] @ W[K,64] + b) ----------------
template <bool RELU, bool WRITE_HALF>
__global__ __launch_bounds__(256)
void gemm128_kernel(const float* __restrict__ A, const float* __restrict__ W,
                    const float* __restrict__ bias, float* __restrict__ C,
                    __half* __restrict__ Yh, int nrows, int K) {
    __shared__ __align__(16) u64 xs[128 * KK];
    __shared__ __align__(16) u64 ws[KK * 32];

    const int tid  = threadIdx.x;
    const int w    = tid >> 5;
    const int lane = tid & 31;
    const int rh   = lane >> 4;
    const int cg   = lane & 15;
    const int rbase = w * 16 + rh * 8;
    const int row0  = blockIdx.x * 128;

    u64 acc[8][2];
    #pragma unroll
    for (int r = 0; r < 8; r++) { acc[r][0] = 0ull; acc[r][1] = 0ull; }

    const int ktiles = (K + KK - 1) / KK;
    for (int t = 0; t < ktiles; t++) {
        const int ko = t * KK;
        #pragma unroll
        for (int i = tid; i < 128 * KK; i += 256) {
            int r  = i >> 3;
            int kk = i & 7;
            int gr = row0 + r;
            int gk = ko + kk;
            float v = (gr < nrows && gk < K) ? __ldg(&A[(long)gr * K + gk]) : 0.f;
            xs[r * KK + kk] = pack2(v, v);
        }
        if (tid < KK * 32) {
            int kk = tid >> 5;
            int p  = tid & 31;
            int gk = ko + kk;
            float w0 = 0.f, w1 = 0.f;
            if (gk < K) { w0 = W[gk * 64 + 2 * p]; w1 = W[gk * 64 + 2 * p + 1]; }
            ws[kk * 32 + p] = pack2(w0, w1);
        }
        __syncthreads();

        u64 wr[KK][2];
        #pragma unroll
        for (int kk = 0; kk < KK; kk++) {
            ulonglong2 wv = *(const ulonglong2*)&ws[kk * 32 + 2 * cg];
            wr[kk][0] = wv.x; wr[kk][1] = wv.y;
        }

        #pragma unroll
        for (int kk2 = 0; kk2 < KK / 2; kk2++) {
            #pragma unroll
            for (int r = 0; r < 8; r++) {
                ulonglong2 xq = *(const ulonglong2*)&xs[(rbase + r) * KK + 2 * kk2];
                FMA2(acc[r][0], xq.x, wr[2 * kk2][0]);
                FMA2(acc[r][1], xq.x, wr[2 * kk2][1]);
                FMA2(acc[r][0], xq.y, wr[2 * kk2 + 1][0]);
                FMA2(acc[r][1], xq.y, wr[2 * kk2 + 1][1]);
            }
        }
        __syncthreads();
    }

    float4 b4 = *(const float4*)&bias[4 * cg];
    #pragma unroll
    for (int r = 0; r < 8; r++) {
        int row = row0 + rbase + r;
        if (row < nrows) {
            float c0, c1, c2, c3;
            unpack2(c0, c1, acc[r][0]);
            unpack2(c2, c3, acc[r][1]);
            c0 += b4.x; c1 += b4.y; c2 += b4.z; c3 += b4.w;
            if (RELU) {
                c0 = fmaxf(c0, 0.f); c1 = fmaxf(c1, 0.f);
                c2 = fmaxf(c2, 0.f); c3 = fmaxf(c3, 0.f);
            }
            *(float4*)&C[(long)row * 64 + 4 * cg] = make_float4(c0, c1, c2, c3);
            if (WRITE_HALF) {
                long yi = (long)row * 64 + 4 * cg;
                *(__half2*)&Yh[yi]     = __floats2half2_rn(c0, c1);
                *(__half2*)&Yh[yi + 2] = __floats2half2_rn(c2, c3);
            }
        }
    }
}

// ---------------- APPNP propagation ----------------
// Warp per node. Lanes 0-15 and 16-31 process DIFFERENT edges of the same
// node concurrently (one shfl + one LDG.64 advances TWO edges). Lane owns 4
// columns: cols 4*(lane&15) .. +3. Cross-half combine at the end via
// shfl_xor(16). Edge = packed u32 (w:15 | src:17); iterate stored fp16.
#define PAIR_STEP(J) {                                                        \
    unsigned pj = __shfl_sync(0xffffffffu, pe, (J), 16);                      \
    unsigned srcj = pj & 0x1FFFFu;                                            \
    float wj = (float)(pj >> 17) * WQ_INV;                                    \
    uint2 v = *(const uint2*)(yin + ((long)srcj << 6) + (hl << 2));           \
    float2 f0 = __half22float2(*(__half2*)&v.x);                              \
    float2 f1 = __half22float2(*(__half2*)&v.y);                              \
    a0 = fmaf(wj, f0.x, a0); a1 = fmaf(wj, f0.y, a1);                         \
    a2 = fmaf(wj, f1.x, a2); a3 = fmaf(wj, f1.y, a3); }

template <bool FINAL>
__global__ __launch_bounds__(256)
void prop_kernel(const __half* __restrict__ yin, const float4* __restrict__ h4,
                 uint2* __restrict__ yout, float4* __restrict__ fout,
                 float c1, float c2) {
    int gtid = blockIdx.x * blockDim.x + threadIdx.x;
    int node = gtid >> 5;
    int lane = threadIdx.x & 31;
    if (node >= N_NODES) return;
    const int hl = lane & 15;

    int beg = g_off[node];
    int end = g_off[node + 1];

    float a0 = 0.f, a1 = 0.f, a2 = 0.f, a3 = 0.f;
    for (int e = beg; e < end; e += 32) {
        int idx = e + lane;
        unsigned pe = (idx < end) ? __ldg(&g_epk[idx]) : 0u;
        int cnt = end - e;
        if (cnt >= 32) {
            #pragma unroll
            for (int j = 0; j < 16; j++) PAIR_STEP(j)
        } else {
            int jcnt = cnt < 16 ? cnt : 16;
            for (int j = 0; j < jcnt; j++) PAIR_STEP(j)
        }
    }
    // combine the two half-warp partial sums
    a0 += __shfl_xor_sync(0xffffffffu, a0, 16);
    a1 += __shfl_xor_sync(0xffffffffu, a1, 16);
    a2 += __shfl_xor_sync(0xffffffffu, a2, 16);
    a3 += __shfl_xor_sync(0xffffffffu, a3, 16);

    if (lane < 16) {
        long oi = (long)node * 16 + hl;
        float4 hv = h4[oi];
        float r0 = fmaf(c1, a0, c2 * hv.x);
        float r1 = fmaf(c1, a1, c2 * hv.y);
        float r2 = fmaf(c1, a2, c2 * hv.z);
        float r3 = fmaf(c1, a3, c2 * hv.w);
        if (FINAL) {
            fout[oi] = make_float4(r0, r1, r2, r3);
        } else {
            __half2 p0 = __floats2half2_rn(r0, r1);
            __half2 p1 = __floats2half2_rn(r2, r3);
            uint2 pv;
            pv.x = *(unsigned*)&p0;
            pv.y = *(unsigned*)&p1;
            yout[oi] = pv;
        }
    }
}

// ---------------- launch ----------------
extern "C" void kernel_launch(void* const* d_in, const int* in_sizes, int n_in,
                              void* d_out, int out_size) {
    const float* x    = (const float*)d_in[0];
    const int*   esrc = (const int*)d_in[1];
    const int*   edst = (const int*)d_in[2];
    const float* ew   = (const float*)d_in[3];
    const float* W1   = (const float*)d_in[4];
    const float* b1   = (const float*)d_in[5];
    const float* W2   = (const float*)d_in[6];
    const float* b2   = (const float*)d_in[7];
    float* out = (float*)d_out;

    static cudaStream_t s_side = nullptr;
    static cudaEvent_t  s_evFork = nullptr, s_evJoin = nullptr;
    if (!s_side) {
        cudaStreamCreateWithFlags(&s_side, cudaStreamNonBlocking);
        cudaEventCreateWithFlags(&s_evFork, cudaEventDisableTiming);
        cudaEventCreateWithFlags(&s_evJoin, cudaEventDisableTiming);
    }

    float *h1_p, *h_p;
    __half *ya_p, *yb_p;
    cudaGetSymbolAddress((void**)&h1_p, g_h1);
    cudaGetSymbolAddress((void**)&h_p,  g_h);
    cudaGetSymbolAddress((void**)&ya_p, g_ya);
    cudaGetSymbolAddress((void**)&yb_p, g_yb);

    // --- fork: CSR build on side stream, concurrent with MLP GEMMs ---
    cudaEventRecord(s_evFork, 0);
    cudaStreamWaitEvent(s_side, s_evFork, 0);

    zero_deg_kernel<<<NSCAN_BLOCKS, 1024, 0, s_side>>>();
    hist_kernel<<<(N_EDGES / 4 + 255) / 256, 256, 0, s_side>>>(edst);
    scan_local_kernel<<<NSCAN_BLOCKS, 1024, 0, s_side>>>();
    scan_top_kernel<<<1, 32, 0, s_side>>>();
    scan_add_kernel<<<NSCAN_BLOCKS, 1024, 0, s_side>>>();
    scatter_kernel<<<(N_EDGES + 255) / 256, 256, 0, s_side>>>(esrc, edst, ew);
    cudaEventRecord(s_evJoin, s_side);

    // --- MLP encoder on main stream (GEMM2 also emits y_0 = fp16(h)) ---
    int gblocks = (N_NODES + 127) / 128;
    gemm128_kernel<true,  false><<<gblocks, 256>>>(x,    W1, b1, h1_p, nullptr, N_NODES, IN_F);
    gemm128_kernel<false, true ><<<gblocks, 256>>>(h1_p, W2, b2, h_p,  ya_p,    N_NODES, HID);

    // --- join, then K propagation steps on scaled fp16 iterate ---
    cudaStreamWaitEvent(0, s_evJoin, 0);

    int pblocks = (N_NODES * 32 + 255) / 256;
    __half* yin  = ya_p;
    __half* yout = yb_p;
    for (int k = 0; k < K_ITERS; k++) {
        if (k < K_ITERS - 1) {
            float c1 = (float)(0.9 * SCALE_S);
            float c2 = (float)(0.1 * pow(SCALE_S, (double)(k + 1)));
            prop_kernel<false><<<pblocks, 256>>>(yin, (const float4*)h_p,
                                                 (uint2*)yout, nullptr, c1, c2);
            __half* t = yin; yin = yout; yout = t;
        } else {
            float c1 = (float)(0.9 * pow(1.0 / SCALE_S, (double)(K_ITERS - 1)));
            float c2 = 0.1f;
            prop_kernel<true><<<pblocks, 256>>>(yin, (const float4*)h_p,
                                                nullptr, (float4*)out, c1, c2);
        }
    }
}